// round 3
// baseline (speedup 1.0000x reference)
#include <cuda_runtime.h>
#include <stdint.h>

#define NB 2
#define NH 4
#define NN 8192
#define NK 32
#define NROWS 8
#define PERM_ELEMS (NB * NN * NH * NK * NK)   // 67,108,864
#define IDX_BASE   PERM_ELEMS

typedef unsigned long long u64;
typedef unsigned int u32;

// Scratch (device globals -> no allocation)
__device__ u64 g_keys[NROWS * NN];
__device__ int g_orderq[NROWS * NN];   // orig index | (eq_with_prev << 13)
__device__ int g_inv  [NROWS * NN];

__device__ __forceinline__ u32 f2u(float f) {
    u32 b = __float_as_uint(f);
    return (b & 0x80000000u) ? ~b : (b | 0x80000000u);
}
__device__ __forceinline__ void cswap(u64& a, u64& b, bool asc) {
    if ((a > b) == asc) { u64 t = a; a = b; b = t; }
}

// -------------------------------------------------------------------------
// Kernel A: sort 2048-tiles. 32 blocks x 512 threads, 4 elems/thread.
// Each warp fully sorts a 128-elem chunk in regs+shfl (k<=128); smem only
// for j>=128 levels of k=256..2048; finishes (j<=64) back in regs/shfl.
// Key = (orderable_val << 32) | row_local_index  -> stable ascending.
// -------------------------------------------------------------------------
__global__ void __launch_bounds__(512) sortA(const float* __restrict__ r) {
    __shared__ u64 sh[2048];
    const unsigned FULL = 0xFFFFFFFFu;
    int tile = blockIdx.x;          // 8 rows x 4 tiles
    int row  = tile >> 2;
    int base = (tile & 3) << 11;    // row-local tile base
    const float* rr = r + row * NN;
    int tid = threadIdx.x, lane = tid & 31, warp = tid >> 5;
    int G = base + warp * 128;      // row-local chunk base

    u64 e[4];
#pragma unroll
    for (int a = 0; a < 4; a++) {
        int gi = G + a * 32 + lane;
        e[a] = ((u64)f2u(rr[gi]) << 32) | (u32)gi;
    }

    // warp-local bitonic sort of 128 elements (k=2..128)
#pragma unroll
    for (int k = 2; k <= 128; k <<= 1) {
#pragma unroll
        for (int j = k >> 1; j > 0; j >>= 1) {
            if (j >= 32) {
                int d = j >> 5;
#pragma unroll
                for (int a = 0; a < 4; a++) if ((a & d) == 0) {
                    bool asc = (((G + a * 32 + lane) & k) == 0);
                    cswap(e[a], e[a | d], asc);
                }
            } else {
#pragma unroll
                for (int a = 0; a < 4; a++) {
                    u64 p = __shfl_xor_sync(FULL, e[a], j);
                    int gi = G + a * 32 + lane;
                    bool low = ((lane & j) == 0);
                    bool asc = ((gi & k) == 0);
                    bool take = (asc == low) ? (p < e[a]) : (p > e[a]);
                    if (take) e[a] = p;
                }
            }
        }
    }
#pragma unroll
    for (int a = 0; a < 4; a++) sh[warp * 128 + a * 32 + lane] = e[a];
    __syncthreads();

    // k=256..2048: smem for j>=128, regs/shfl finish for j<=64
    for (int k = 256; k <= 2048; k <<= 1) {
        for (int j = k >> 1; j >= 128; j >>= 1) {
#pragma unroll
            for (int t = tid; t < 1024; t += 512) {
                int i = ((t & ~(j - 1)) << 1) | (t & (j - 1));
                int p = i | j;
                bool asc = (((base + i) & k) == 0);
                u64 a = sh[i], b = sh[p];
                if ((a > b) == asc) { sh[i] = b; sh[p] = a; }
            }
            __syncthreads();
        }
#pragma unroll
        for (int a = 0; a < 4; a++) e[a] = sh[warp * 128 + a * 32 + lane];
        bool asc = (((base + warp * 128) & k) == 0);   // uniform per chunk (k>=256)
        cswap(e[0], e[2], asc); cswap(e[1], e[3], asc);   // j=64
        cswap(e[0], e[1], asc); cswap(e[2], e[3], asc);   // j=32
#pragma unroll
        for (int j = 16; j > 0; j >>= 1) {
#pragma unroll
            for (int a = 0; a < 4; a++) {
                u64 p = __shfl_xor_sync(FULL, e[a], j);
                bool low = ((lane & j) == 0);
                bool take = (asc == low) ? (p < e[a]) : (p > e[a]);
                if (take) e[a] = p;
            }
        }
        if (k < 2048) {
#pragma unroll
            for (int a = 0; a < 4; a++) sh[warp * 128 + a * 32 + lane] = e[a];
            __syncthreads();
        } else {
            u64* gk = g_keys + row * NN + base;
#pragma unroll
            for (int a = 0; a < 4; a++) gk[warp * 128 + a * 32 + lane] = e[a];
        }
    }
}

// -------------------------------------------------------------------------
// Kernel B: per-row merge k=4096 + k=8192 in 4 register phases + extract.
// 8 blocks x 512 threads, 16 elems/thread, 64KB dynamic smem.
//   P1: stride-512 ownership -> k=4096 j=2048,1024,512 in regs
//   P2: chunk ownership      -> k=4096 j=256..32 regs, j=16..1 shfl
//   P3: stride-512           -> k=8192 j=4096..512 in regs
//   P4: chunk                -> k=8192 j=256..1, then extract orderq/inv
// -------------------------------------------------------------------------
__global__ void __launch_bounds__(512) mergeB() {
    extern __shared__ u64 sh[];
    const unsigned FULL = 0xFFFFFFFFu;
    int row = blockIdx.x, tid = threadIdx.x, lane = tid & 31, warp = tid >> 5;
    const u64* gk = g_keys + row * NN;
    for (int i = tid; i < NN; i += 512) sh[i] = gk[i];
    __syncthreads();

    u64 e[16];
    // ---- P1: k=4096, j=2048,1024,512 ----
#pragma unroll
    for (int m = 0; m < 16; m++) e[m] = sh[tid + (m << 9)];
#pragma unroll
    for (int m = 0; m < 16; m++) if ((m & 4) == 0) cswap(e[m], e[m | 4], m < 8);
#pragma unroll
    for (int m = 0; m < 16; m++) if ((m & 2) == 0) cswap(e[m], e[m | 2], m < 8);
#pragma unroll
    for (int m = 0; m < 16; m++) if ((m & 1) == 0) cswap(e[m], e[m | 1], m < 8);
#pragma unroll
    for (int m = 0; m < 16; m++) sh[tid + (m << 9)] = e[m];
    __syncthreads();

    // ---- P2: k=4096, j=256..1 ----
    int chunk = warp << 9;
    {
#pragma unroll
        for (int m = 0; m < 16; m++) e[m] = sh[chunk + (m << 5) + lane];
        bool asc = ((chunk & 4096) == 0);
#pragma unroll
        for (int m = 0; m < 16; m++) if ((m & 8) == 0) cswap(e[m], e[m | 8], asc); // j=256
#pragma unroll
        for (int m = 0; m < 16; m++) if ((m & 4) == 0) cswap(e[m], e[m | 4], asc); // j=128
#pragma unroll
        for (int m = 0; m < 16; m++) if ((m & 2) == 0) cswap(e[m], e[m | 2], asc); // j=64
#pragma unroll
        for (int m = 0; m < 16; m++) if ((m & 1) == 0) cswap(e[m], e[m | 1], asc); // j=32
#pragma unroll
        for (int j = 16; j > 0; j >>= 1) {
#pragma unroll
            for (int m = 0; m < 16; m++) {
                u64 p = __shfl_xor_sync(FULL, e[m], j);
                bool low = ((lane & j) == 0);
                bool take = (asc == low) ? (p < e[m]) : (p > e[m]);
                if (take) e[m] = p;
            }
        }
#pragma unroll
        for (int m = 0; m < 16; m++) sh[chunk + (m << 5) + lane] = e[m];
    }
    __syncthreads();

    // ---- P3: k=8192, j=4096,2048,1024,512 (asc everywhere) ----
#pragma unroll
    for (int m = 0; m < 16; m++) e[m] = sh[tid + (m << 9)];
#pragma unroll
    for (int m = 0; m < 16; m++) if ((m & 8) == 0) cswap(e[m], e[m | 8], true);
#pragma unroll
    for (int m = 0; m < 16; m++) if ((m & 4) == 0) cswap(e[m], e[m | 4], true);
#pragma unroll
    for (int m = 0; m < 16; m++) if ((m & 2) == 0) cswap(e[m], e[m | 2], true);
#pragma unroll
    for (int m = 0; m < 16; m++) if ((m & 1) == 0) cswap(e[m], e[m | 1], true);
#pragma unroll
    for (int m = 0; m < 16; m++) sh[tid + (m << 9)] = e[m];
    __syncthreads();

    // ---- P4: k=8192, j=256..1 ----
    {
#pragma unroll
        for (int m = 0; m < 16; m++) e[m] = sh[chunk + (m << 5) + lane];
#pragma unroll
        for (int m = 0; m < 16; m++) if ((m & 8) == 0) cswap(e[m], e[m | 8], true);
#pragma unroll
        for (int m = 0; m < 16; m++) if ((m & 4) == 0) cswap(e[m], e[m | 4], true);
#pragma unroll
        for (int m = 0; m < 16; m++) if ((m & 2) == 0) cswap(e[m], e[m | 2], true);
#pragma unroll
        for (int m = 0; m < 16; m++) if ((m & 1) == 0) cswap(e[m], e[m | 1], true);
#pragma unroll
        for (int j = 16; j > 0; j >>= 1) {
#pragma unroll
            for (int m = 0; m < 16; m++) {
                u64 p = __shfl_xor_sync(FULL, e[m], j);
                bool low = ((lane & j) == 0);
                bool take = low ? (p < e[m]) : (p > e[m]);
                if (take) e[m] = p;
            }
        }
#pragma unroll
        for (int m = 0; m < 16; m++) sh[chunk + (m << 5) + lane] = e[m];
    }
    __syncthreads();

    // ---- extract: orderq (idx | eq<<13) and inverse permutation ----
    int* oq  = g_orderq + row * NN;
    int* inv = g_inv    + row * NN;
    for (int i = tid; i < NN; i += 512) {
        u64 key = sh[i];
        int pos = (int)(u32)key;                 // original row-local index
        int eq  = 0;
        if (i > 0) eq = ((u32)(key >> 32) == (u32)(sh[i - 1] >> 32)) ? 1 : 0;
        oq[i]    = pos | (eq << 13);
        inv[pos] = i;
    }
}

// -------------------------------------------------------------------------
// Windows + perm generation: one warp per window.
// Rank from slot arithmetic (window is a contiguous slice of the sorted
// array): rank[t] = greater(m, t1) + (t - t0), tie runs from eq-bit ballot.
// Bitonic sorts a single packed int (idx<<6 | rank). float4 stores.
// -------------------------------------------------------------------------
__global__ void __launch_bounds__(256) windowsW(float* __restrict__ out) {
    const unsigned FULL = 0xFFFFFFFFu;
    int w    = blockIdx.x * 8 + (threadIdx.x >> 5);
    int lane = threadIdx.x & 31;
    int row  = w >> 13;
    int p    = w & (NN - 1);
    int rb   = row * NN;

    int s   = g_inv[rb + p];
    int pos = (s + lane) & (NN - 1);
    int q   = g_orderq[rb + pos];
    int idx = q & 8191;
    int eq  = (q >> 13) & 1;

    unsigned mask = __ballot_sync(FULL, eq) & ~1u;   // slot0 is always a run start
    int t = lane;
    unsigned above = (t == 31) ? 0u : (mask >> (t + 1));
    int t1 = t + (__ffs(~above) - 1);                // run end
    unsigned below = ~mask & (0xFFFFFFFFu >> (31 - t));
    int t0 = 31 - __clz(below);                      // run start
    int m  = NN - s; if (m > 32) m = 32;             // wrap point
    int greater = (t < m) ? (m - 1 - t1) : (m + 31 - t1);
    int rank = greater + (t - t0);

    int pack = (idx << 6) | rank;                    // idx distinct -> stable
#pragma unroll
    for (int k2 = 2; k2 <= 32; k2 <<= 1) {
#pragma unroll
        for (int j = k2 >> 1; j > 0; j >>= 1) {
            int o = __shfl_xor_sync(FULL, pack, j);
            bool asc = ((lane & k2) == 0);
            bool low = ((lane & j) == 0);
            bool take = (asc == low) ? (o < pack) : (o > pack);
            if (take) pack = o;
        }
    }

    out[(size_t)IDX_BASE + (size_t)(rb + p) * NK + lane] = (float)(pack >> 6);
    int rk = pack & 63;

    float e = __expf(-2.0f * (float)lane);           // lane m holds exp(-2m)
    int c0 = (lane & 7) * 4;
    int r0 = __shfl_sync(FULL, rk, c0);
    int r1 = __shfl_sync(FULL, rk, c0 + 1);
    int r2 = __shfl_sync(FULL, rk, c0 + 2);
    int r3 = __shfl_sync(FULL, rk, c0 + 3);
    int arow = lane >> 3;

    int b = row >> 2, h = row & 3;
    float* po = out + ((size_t)((b * NN + p) * NH + h) << 10);  // (B,N,H,K,K)
#pragma unroll
    for (int rnd = 0; rnd < 8; rnd++) {
        int a = rnd * 4 + arow;
        float4 v;
        v.x = __shfl_sync(FULL, e, (a - r0) & 31);
        v.y = __shfl_sync(FULL, e, (a - r1) & 31);
        v.z = __shfl_sync(FULL, e, (a - r2) & 31);
        v.w = __shfl_sync(FULL, e, (a - r3) & 31);
        *reinterpret_cast<float4*>(po + a * 32 + c0) = v;
    }
}

extern "C" void kernel_launch(void* const* d_in, const int* in_sizes, int n_in,
                              void* d_out, int out_size) {
    const float* ranking = (const float*)d_in[0];   // (B,H,N,1) f32
    float* out = (float*)d_out;

    static bool attr_set = false;
    if (!attr_set) {
        cudaFuncSetAttribute(mergeB, cudaFuncAttributeMaxDynamicSharedMemorySize,
                             NN * sizeof(u64));
        attr_set = true;
    }

    sortA<<<32, 512>>>(ranking);
    mergeB<<<8, 512, NN * sizeof(u64)>>>();
    windowsW<<<8192, 256>>>(out);
}

// round 5
// speedup vs baseline: 1.1727x; 1.1727x over previous
#include <cuda_runtime.h>
#include <stdint.h>

#define NB 2
#define NH 4
#define NN 8192
#define NK 32
#define NROWS 8
#define PERM_ELEMS (NB * NN * NH * NK * NK)   // 67,108,864
#define IDX_BASE   PERM_ELEMS

typedef unsigned long long u64;
typedef unsigned int u32;

// Scratch (device globals -> no allocation)
__device__ u64 g_keys[NROWS * NN];
__device__ int g_inv [NROWS * NN];

__device__ __forceinline__ u32 f2u(float f) {
    u32 b = __float_as_uint(f);
    return (b & 0x80000000u) ? ~b : (b | 0x80000000u);
}
__device__ __forceinline__ void cswap(u64& a, u64& b, bool asc) {
    if ((a > b) == asc) { u64 t = a; a = b; b = t; }
}

// -------------------------------------------------------------------------
// Kernel 1: sort 2048-tiles in smem (k=2..2048). 32 blocks x 512 threads.
// Direction from the global bitonic bit so tiles are merge-ready.
// Key = (orderable_value << 32) | row_local_index -> stable ascending.
// -------------------------------------------------------------------------
__global__ void __launch_bounds__(512) sortTiles(const float* __restrict__ r) {
    __shared__ u64 sh[2048];
    int tile = blockIdx.x;           // 8 rows x 4 tiles
    int row  = tile >> 2;
    int base = (tile & 3) << 11;
    const float* rr = r + row * NN;
    int tid = threadIdx.x;

    for (int l = tid; l < 2048; l += 512) {
        int gi = base + l;
        sh[l] = ((u64)f2u(rr[gi]) << 32) | (u32)gi;
    }
    __syncthreads();

    for (int k = 2; k <= 2048; k <<= 1) {
        for (int j = k >> 1; j > 0; j >>= 1) {
            for (int t = tid; t < 1024; t += 512) {
                int i = ((t & ~(j - 1)) << 1) | (t & (j - 1));
                int p = i | j;
                bool asc = (((base + i) & k) == 0);
                u64 a = sh[i], b = sh[p];
                if ((a > b) == asc) { sh[i] = b; sh[p] = a; }
            }
            __syncthreads();
        }
    }

    u64* kk = g_keys + row * NN + base;
    for (int l = tid; l < 2048; l += 512) kk[l] = sh[l];
}

// -------------------------------------------------------------------------
// Kernel 2: one block per row; whole row (64KB) in smem, so k=4096 AND
// k=8192 merges are both block-local (no grid sync, no extra launches).
//   reg phase (e[16] @ stride 512): k=4096 j=2048,1024,512
//   smem steps: k=4096 j=256..1
//   reg phase: k=8192 j=4096,2048,1024,512
//   smem steps: k=8192 j=256..1
// Extracts sorted keys + inverse permutation.
// -------------------------------------------------------------------------
__global__ void __launch_bounds__(512) mergeRows() {
    extern __shared__ u64 sh[];
    int row = blockIdx.x, tid = threadIdx.x;
    u64* gk = g_keys + row * NN;
    for (int i = tid; i < NN; i += 512) sh[i] = gk[i];
    __syncthreads();

    u64 e[16];

    // ---- k=4096: j=2048,1024,512 in registers (i bit9..12 = m bit0..3) ----
#pragma unroll
    for (int m = 0; m < 16; m++) e[m] = sh[tid + (m << 9)];
    {
        // asc = ((i & 4096) == 0)  <=>  (m & 8) == 0
#pragma unroll
        for (int m = 0; m < 16; m++) if ((m & 4) == 0) cswap(e[m], e[m | 4], (m & 8) == 0);
#pragma unroll
        for (int m = 0; m < 16; m++) if ((m & 2) == 0) cswap(e[m], e[m | 2], (m & 8) == 0);
#pragma unroll
        for (int m = 0; m < 16; m++) if ((m & 1) == 0) cswap(e[m], e[m | 1], (m & 8) == 0);
    }
#pragma unroll
    for (int m = 0; m < 16; m++) sh[tid + (m << 9)] = e[m];
    __syncthreads();

    // ---- k=4096: j=256..1 in smem ----
    for (int j = 256; j > 0; j >>= 1) {
#pragma unroll
        for (int t = tid; t < 4096; t += 512) {
            int i = ((t & ~(j - 1)) << 1) | (t & (j - 1));
            int p = i | j;
            bool asc = ((i & 4096) == 0);
            u64 a = sh[i], b = sh[p];
            if ((a > b) == asc) { sh[i] = b; sh[p] = a; }
        }
        __syncthreads();
    }

    // ---- k=8192: j=4096,2048,1024,512 in registers (asc everywhere) ----
#pragma unroll
    for (int m = 0; m < 16; m++) e[m] = sh[tid + (m << 9)];
#pragma unroll
    for (int m = 0; m < 16; m++) if ((m & 8) == 0) cswap(e[m], e[m | 8], true);
#pragma unroll
    for (int m = 0; m < 16; m++) if ((m & 4) == 0) cswap(e[m], e[m | 4], true);
#pragma unroll
    for (int m = 0; m < 16; m++) if ((m & 2) == 0) cswap(e[m], e[m | 2], true);
#pragma unroll
    for (int m = 0; m < 16; m++) if ((m & 1) == 0) cswap(e[m], e[m | 1], true);
#pragma unroll
    for (int m = 0; m < 16; m++) sh[tid + (m << 9)] = e[m];
    __syncthreads();

    // ---- k=8192: j=256..1 in smem ----
    for (int j = 256; j > 0; j >>= 1) {
#pragma unroll
        for (int t = tid; t < 4096; t += 512) {
            int i = ((t & ~(j - 1)) << 1) | (t & (j - 1));
            int p = i | j;
            u64 a = sh[i], b = sh[p];
            if (a > b) { sh[i] = b; sh[p] = a; }
        }
        __syncthreads();
    }

    // ---- extract: sorted keys + inverse permutation ----
    int* inv = g_inv + row * NN;
    for (int i = tid; i < NN; i += 512) {
        u64 key = sh[i];
        gk[i] = key;
        inv[(int)((u32)key & 8191u)] = i;
    }
}

// -------------------------------------------------------------------------
// Kernel 3: windows + perm generation, one warp per window (65536 warps).
//   - one u64 gather per lane: value bits (ties) AND original index
//   - rank via slot arithmetic: window is a contiguous slice of the sorted
//     array -> rank[t] = greater(m, t1) + (t - t0); tie runs from ballot of
//     eq bits (shfl_up of comparable value bits)
//   - bitonic re-sort by index on a packed int (idx<<6 | rank)
//   - perm values via per-lane exp table + shfl; float4 streaming stores
// -------------------------------------------------------------------------
__global__ void __launch_bounds__(256) windowsW(float* __restrict__ out) {
    const unsigned FULL = 0xFFFFFFFFu;
    int w    = blockIdx.x * 8 + (threadIdx.x >> 5);
    int lane = threadIdx.x & 31;
    int row  = w >> 13;
    int p    = w & (NN - 1);
    int rb   = row * NN;

    int s   = g_inv[rb + p];
    int pos = (s + lane) & (NN - 1);
    u64 key = g_keys[rb + pos];
    int idx = (int)((u32)key & 8191u);
    u32 u   = (u32)(key >> 32);

    // eq bit vs previous window slot; slot 0 and the wrap slot break runs
    u32 prevu = __shfl_up_sync(FULL, u, 1);
    int eq = (lane > 0 && pos != 0 && u == prevu) ? 1 : 0;
    unsigned mask = __ballot_sync(FULL, eq);

    int t = lane;
    unsigned above = (t == 31) ? 0u : (mask >> (t + 1));
    int t1 = t + (__ffs(~above) - 1);                // tie-run end
    unsigned below = ~mask & (0xFFFFFFFFu >> (31 - t));
    int t0 = 31 - __clz(below);                      // tie-run start
    int m  = NN - s; if (m > 32) m = 32;             // wrap point
    int greater = (t < m) ? (m - 1 - t1) : (m + 31 - t1);
    int rank = greater + (t - t0);

    int pack = (idx << 6) | rank;                    // idx distinct -> stable
#pragma unroll
    for (int k2 = 2; k2 <= 32; k2 <<= 1) {
#pragma unroll
        for (int j = k2 >> 1; j > 0; j >>= 1) {
            int o = __shfl_xor_sync(FULL, pack, j);
            bool asc = ((lane & k2) == 0);
            bool low = ((lane & j) == 0);
            bool take = (asc == low) ? (o < pack) : (o > pack);
            if (take) pack = o;
        }
    }

    __stcs(out + (size_t)IDX_BASE + (size_t)(rb + p) * NK + lane,
           (float)(pack >> 6));
    int rk = pack & 63;

    float e = __expf(-2.0f * (float)lane);           // lane m holds exp(-2m)
    int c0 = (lane & 7) * 4;
    int r0 = __shfl_sync(FULL, rk, c0);
    int r1 = __shfl_sync(FULL, rk, c0 + 1);
    int r2 = __shfl_sync(FULL, rk, c0 + 2);
    int r3 = __shfl_sync(FULL, rk, c0 + 3);
    int arow = lane >> 3;

    int b = row >> 2, h = row & 3;
    float* po = out + ((size_t)((b * NN + p) * NH + h) << 10);  // (B,N,H,K,K)
#pragma unroll
    for (int rnd = 0; rnd < 8; rnd++) {
        int a = rnd * 4 + arow;
        float4 v;
        v.x = __shfl_sync(FULL, e, (a - r0) & 31);
        v.y = __shfl_sync(FULL, e, (a - r1) & 31);
        v.z = __shfl_sync(FULL, e, (a - r2) & 31);
        v.w = __shfl_sync(FULL, e, (a - r3) & 31);
        __stcs(reinterpret_cast<float4*>(po + a * 32 + c0), v);
    }
}

extern "C" void kernel_launch(void* const* d_in, const int* in_sizes, int n_in,
                              void* d_out, int out_size) {
    const float* ranking = (const float*)d_in[0];   // (B,H,N,1) f32
    float* out = (float*)d_out;

    cudaFuncSetAttribute(mergeRows, cudaFuncAttributeMaxDynamicSharedMemorySize,
                         NN * sizeof(u64));

    sortTiles<<<32, 512>>>(ranking);
    mergeRows<<<NROWS, 512, NN * sizeof(u64)>>>();
    windowsW<<<8192, 256>>>(out);
}

// round 6
// speedup vs baseline: 1.5488x; 1.3207x over previous
#include <cuda_runtime.h>
#include <stdint.h>

#define NB 2
#define NH 4
#define NN 8192
#define NK 32
#define NROWS 8
#define PERM_ELEMS (NB * NN * NH * NK * NK)   // 67,108,864
#define IDX_BASE   PERM_ELEMS

typedef unsigned long long u64;
typedef unsigned int u32;

// Scratch (device globals -> no allocation)
__device__ u64 g_keys[NROWS * NN];
__device__ int g_inv [NROWS * NN];

__device__ __forceinline__ u32 f2u(float f) {
    u32 b = __float_as_uint(f);
    return (b & 0x80000000u) ? ~b : (b | 0x80000000u);
}

__device__ __forceinline__ void cluster_sync() {
    asm volatile("barrier.cluster.arrive.aligned;" ::: "memory");
    asm volatile("barrier.cluster.wait.aligned;" ::: "memory");
}

__device__ __forceinline__ u32 smem_u32(const void* p) {
    u32 a;
    asm("{ .reg .u64 t; cvta.to.shared.u64 t, %1; cvt.u32.u64 %0, t; }"
        : "=r"(a) : "l"(p));
    return a;
}

__device__ __forceinline__ u32 mapa_rank(u32 local, u32 rank) {
    u32 r;
    asm("mapa.shared::cluster.u32 %0, %1, %2;" : "=r"(r) : "r"(local), "r"(rank));
    return r;
}

// One bitonic compare-exchange step inside a warp-private 128-elem segment
// (valid for j <= 64). Only __syncwarp needed.
__device__ __forceinline__ void warp_step(u64* sh, int seg, int gseg,
                                          int lane, int j, int k) {
#pragma unroll
    for (int t = lane; t < 64; t += 32) {
        int i = ((t & ~(j - 1)) << 1) | (t & (j - 1));
        int p = i | j;
        bool asc = (((gseg + i) & k) == 0);
        u64 a = sh[seg + i], b = sh[seg + p];
        if ((a > b) == asc) { sh[seg + i] = b; sh[seg + p] = a; }
    }
    __syncwarp();
}

// Block-wide step over the 2048-elem chunk (j >= 128).
__device__ __forceinline__ void block_step(u64* sh, int gbase, int tid,
                                           int j, int k) {
#pragma unroll
    for (int t = tid; t < 1024; t += 512) {
        int i = ((t & ~(j - 1)) << 1) | (t & (j - 1));
        int p = i | j;
        bool asc = (((gbase + i) & k) == 0);
        u64 a = sh[i], b = sh[p];
        if ((a > b) == asc) { sh[i] = b; sh[p] = a; }
    }
    __syncthreads();
}

// Cross-CTA exchange via DSMEM: pairwise min/max with the partner CTA's
// same-offset element. Keys are unique -> both sides decide consistently.
__device__ __forceinline__ void exchange(u64* sh, u32 shbase, int partner,
                                         bool keep_min, int tid) {
    cluster_sync();                         // peer chunk complete
    u64 peer[4];
    u32 remote = mapa_rank(shbase, (u32)partner);
#pragma unroll
    for (int m = 0; m < 4; m++) {
        u32 addr = remote + (u32)((tid + (m << 9)) << 3);
        asm volatile("ld.shared::cluster.b64 %0, [%1];" : "=l"(peer[m]) : "r"(addr));
    }
    cluster_sync();                         // all reads done before overwrite
#pragma unroll
    for (int m = 0; m < 4; m++) {
        int l = tid + (m << 9);
        u64 mine = sh[l];
        bool take = keep_min ? (peer[m] < mine) : (peer[m] > mine);
        if (take) sh[l] = peer[m];
    }
}

// -------------------------------------------------------------------------
// Full stable argsort of 8 rows x 8192, ONE launch.
// 8 clusters x 4 CTAs; each CTA owns a 2048-chunk in smem end-to-end.
//   tile sort k=2..2048: j<=64 warp-local (syncwarp), j>=128 block-wide
//   k=4096: j=2048 DSMEM exchange, j<=1024 local
//   k=8192: j=4096 & j=2048 DSMEM exchanges, j<=1024 local
// Extracts sorted keys + inverse permutation.
// -------------------------------------------------------------------------
__global__ void __launch_bounds__(512) __cluster_dims__(4, 1, 1)
sortCluster(const float* __restrict__ r) {
    __shared__ u64 sh[2048];
    int tid  = threadIdx.x, lane = tid & 31, warp = tid >> 5;
    int row  = blockIdx.x >> 2;
    int rank = blockIdx.x & 3;
    int base = rank << 11;                  // row-global offset of this chunk
    const float* rr = r + row * NN;
    u32 shbase = smem_u32(sh);

    for (int l = tid; l < 2048; l += 512) {
        int gi = base + l;
        sh[l] = ((u64)f2u(rr[gi]) << 32) | (u32)gi;   // stable asc key
    }
    __syncthreads();

    int seg  = warp << 7;                   // warp-private 128-elem segment
    int gseg = base + seg;

    // k = 2..128: fully warp-local
    for (int k = 2; k <= 128; k <<= 1)
        for (int j = k >> 1; j > 0; j >>= 1)
            warp_step(sh, seg, gseg, lane, j, k);
    __syncthreads();

    // k = 256..2048: block steps for j>=128, warp-local finish
    for (int k = 256; k <= 2048; k <<= 1) {
        for (int j = k >> 1; j >= 128; j >>= 1)
            block_step(sh, base, tid, j, k);
        for (int j = 64; j > 0; j >>= 1)
            warp_step(sh, seg, gseg, lane, j, k);
        __syncthreads();
    }

    // ---- k=4096: cross-CTA j=2048, then local j=1024..1 ----
    // pair {0,1} ascending, {2,3} descending -> keep_min: 0,3 = min; 1,2 = max
    exchange(sh, shbase, rank ^ 1, ((rank ^ (rank >> 1)) & 1) == 0, tid);
    for (int j = 1024; j >= 128; j >>= 1)
        block_step(sh, base, tid, j, 4096);
    for (int j = 64; j > 0; j >>= 1)
        warp_step(sh, seg, gseg, lane, j, 4096);
    __syncthreads();

    // ---- k=8192 (all ascending): cross j=4096, j=2048, local j=1024..1 ----
    exchange(sh, shbase, rank ^ 2, rank < 2, tid);
    exchange(sh, shbase, rank ^ 1, (rank & 1) == 0, tid);
    for (int j = 1024; j >= 128; j >>= 1)
        block_step(sh, base, tid, j, 8192);
    for (int j = 64; j > 0; j >>= 1)
        warp_step(sh, seg, gseg, lane, j, 8192);
    __syncthreads();

    // ---- extract sorted keys + inverse permutation ----
    u64* gk  = g_keys + row * NN + base;
    int* inv = g_inv  + row * NN;
    for (int l = tid; l < 2048; l += 512) {
        u64 key = sh[l];
        gk[l] = key;
        inv[(u32)key & 8191u] = base + l;
    }
}

// -------------------------------------------------------------------------
// Windows + perm generation (validated in R3/R5): one warp per window.
// Rank via slot arithmetic on the sorted slice; bitonic re-sort by index on
// a packed int; perm values via per-lane exp table + shfl; stcs stores.
// -------------------------------------------------------------------------
__global__ void __launch_bounds__(256) windowsW(float* __restrict__ out) {
    const unsigned FULL = 0xFFFFFFFFu;
    int w    = blockIdx.x * 8 + (threadIdx.x >> 5);
    int lane = threadIdx.x & 31;
    int row  = w >> 13;
    int p    = w & (NN - 1);
    int rb   = row * NN;

    int s   = g_inv[rb + p];
    int pos = (s + lane) & (NN - 1);
    u64 key = g_keys[rb + pos];
    int idx = (int)((u32)key & 8191u);
    u32 u   = (u32)(key >> 32);

    u32 prevu = __shfl_up_sync(FULL, u, 1);
    int eq = (lane > 0 && pos != 0 && u == prevu) ? 1 : 0;
    unsigned mask = __ballot_sync(FULL, eq);

    int t = lane;
    unsigned above = (t == 31) ? 0u : (mask >> (t + 1));
    int t1 = t + (__ffs(~above) - 1);                // tie-run end
    unsigned below = ~mask & (0xFFFFFFFFu >> (31 - t));
    int t0 = 31 - __clz(below);                      // tie-run start
    int m  = NN - s; if (m > 32) m = 32;             // wrap point
    int greater = (t < m) ? (m - 1 - t1) : (m + 31 - t1);
    int rank = greater + (t - t0);

    int pack = (idx << 6) | rank;                    // idx distinct -> stable
#pragma unroll
    for (int k2 = 2; k2 <= 32; k2 <<= 1) {
#pragma unroll
        for (int j = k2 >> 1; j > 0; j >>= 1) {
            int o = __shfl_xor_sync(FULL, pack, j);
            bool asc = ((lane & k2) == 0);
            bool low = ((lane & j) == 0);
            bool take = (asc == low) ? (o < pack) : (o > pack);
            if (take) pack = o;
        }
    }

    __stcs(out + (size_t)IDX_BASE + (size_t)(rb + p) * NK + lane,
           (float)(pack >> 6));
    int rk = pack & 63;

    float e = __expf(-2.0f * (float)lane);           // lane m holds exp(-2m)
    int c0 = (lane & 7) * 4;
    int r0 = __shfl_sync(FULL, rk, c0);
    int r1 = __shfl_sync(FULL, rk, c0 + 1);
    int r2 = __shfl_sync(FULL, rk, c0 + 2);
    int r3 = __shfl_sync(FULL, rk, c0 + 3);
    int arow = lane >> 3;

    int b = row >> 2, h = row & 3;
    float* po = out + ((size_t)((b * NN + p) * NH + h) << 10);  // (B,N,H,K,K)
#pragma unroll
    for (int rnd = 0; rnd < 8; rnd++) {
        int a = rnd * 4 + arow;
        float4 v;
        v.x = __shfl_sync(FULL, e, (a - r0) & 31);
        v.y = __shfl_sync(FULL, e, (a - r1) & 31);
        v.z = __shfl_sync(FULL, e, (a - r2) & 31);
        v.w = __shfl_sync(FULL, e, (a - r3) & 31);
        __stcs(reinterpret_cast<float4*>(po + a * 32 + c0), v);
    }
}

extern "C" void kernel_launch(void* const* d_in, const int* in_sizes, int n_in,
                              void* d_out, int out_size) {
    const float* ranking = (const float*)d_in[0];   // (B,H,N,1) f32
    float* out = (float*)d_out;

    sortCluster<<<32, 512>>>(ranking);
    windowsW<<<8192, 256>>>(out);
}